// round 8
// baseline (speedup 1.0000x reference)
#include <cuda_runtime.h>
#include <math.h>
#include <math_constants.h>
#include <stdint.h>

#define BSZ  128
#define TLEN 500
#define ISZ  700
#define HSZ  256
#define OSZ  20
#define BJ0  0.01f

// Scratch. g_hpre layout: [b][t][n]
__device__ float g_hpre[(size_t)BSZ * TLEN * HSZ];
__device__ float g_wit[ISZ * HSZ];                  // W_i2h^T [700][256]
__device__ float g_wth[HSZ * HSZ];                  // W_h2h^T [j][i]

// ---------------------------------------------------------------------------
__global__ void prep_kernel(const float* __restrict__ Wi,
                            const float* __restrict__ Wh) {
    int idx = blockIdx.x * blockDim.x + threadIdx.x;
    if (idx < ISZ * HSZ) {
        int k = idx / HSZ, n = idx % HSZ;
        g_wit[idx] = Wi[n * ISZ + k];
    }
    if (idx < HSZ * HSZ) {
        int j = idx / HSZ, i = idx % HSZ;
        g_wth[idx] = Wh[i * HSZ + j];
    }
}

// ---------------------------------------------------------------------------
// Persistent GEMM (R4 exact; bitwise-identical hpre)
// ---------------------------------------------------------------------------
#define FMA2(acc, a, b) \
    asm("fma.rn.f32x2 %0, %1, %2, %0;" : "+l"(acc) : "l"(a), "l"(b))

#define GEMM_TILES 1000
#define GEMM_GRID  296

__global__ void __launch_bounds__(256, 2) gemm_kernel(
    const float* __restrict__ A,
    const float* __restrict__ bi,
    const float* __restrict__ bh) {
    const int N = HSZ, K = ISZ;
    __shared__ __align__(16) float As[2][8][128];
    __shared__ __align__(16) float Bs[2][8][128];

    int tid = threadIdx.x;
    int tx = tid & 15, ty = tid >> 4;
    int arow  = tid >> 1,  acol4 = (tid & 1) * 4;
    int brow  = tid >> 5,  bcol4 = (tid & 31) * 4;

    for (int tile = blockIdx.x; tile < GEMM_TILES; tile += GEMM_GRID) {
        int bm = (tile >> 1) * 128;
        int bn = (tile & 1) * 128;
        const float* Aptr = A + (size_t)(bm + arow) * K;

        unsigned long long acc2[8][4];
#pragma unroll
        for (int i = 0; i < 8; i++)
#pragma unroll
            for (int j = 0; j < 4; j++) acc2[i][j] = 0ull;

        {
            float4 av = make_float4(0.f, 0.f, 0.f, 0.f);
            float4 bv = make_float4(0.f, 0.f, 0.f, 0.f);
            if (acol4 < K) av = *(const float4*)(Aptr + acol4);
            if (brow  < K) bv = *(const float4*)(g_wit + (size_t)brow * N + bn + bcol4);
            As[0][acol4 + 0][arow] = av.x;
            As[0][acol4 + 1][arow] = av.y;
            As[0][acol4 + 2][arow] = av.z;
            As[0][acol4 + 3][arow] = av.w;
            *(float4*)&Bs[0][brow][bcol4] = bv;
        }
        __syncthreads();

        int p = 0;
        for (int k0 = 0; k0 < K; k0 += 8) {
            bool more = (k0 + 8) < K;
            float4 av2 = make_float4(0.f, 0.f, 0.f, 0.f);
            float4 bv2 = make_float4(0.f, 0.f, 0.f, 0.f);
            if (more) {
                int ac = k0 + 8 + acol4;
                int bk = k0 + 8 + brow;
                if (ac < K) av2 = *(const float4*)(Aptr + ac);
                if (bk < K) bv2 = *(const float4*)(g_wit + (size_t)bk * N + bn + bcol4);
            }
#pragma unroll
            for (int kk = 0; kk < 8; kk++) {
                float4 a0 = *(const float4*)&As[p][kk][ty * 8];
                float4 a1 = *(const float4*)&As[p][kk][ty * 8 + 4];
                const unsigned long long* bp =
                    (const unsigned long long*)&Bs[p][kk][tx * 8];
                unsigned long long bb0 = bp[0], bb1 = bp[1], bb2 = bp[2], bb3 = bp[3];
                float af[8] = {a0.x, a0.y, a0.z, a0.w, a1.x, a1.y, a1.z, a1.w};
#pragma unroll
                for (int i = 0; i < 8; i++) {
                    unsigned long long aa;
                    unsigned ai = __float_as_uint(af[i]);
                    asm("mov.b64 %0, {%1, %1};" : "=l"(aa) : "r"(ai));
                    FMA2(acc2[i][0], aa, bb0);
                    FMA2(acc2[i][1], aa, bb1);
                    FMA2(acc2[i][2], aa, bb2);
                    FMA2(acc2[i][3], aa, bb3);
                }
            }
            if (more) {
                As[p ^ 1][acol4 + 0][arow] = av2.x;
                As[p ^ 1][acol4 + 1][arow] = av2.y;
                As[p ^ 1][acol4 + 2][arow] = av2.z;
                As[p ^ 1][acol4 + 3][arow] = av2.w;
                *(float4*)&Bs[p ^ 1][brow][bcol4] = bv2;
            }
            __syncthreads();
            p ^= 1;
        }

        float biasv[8];
#pragma unroll
        for (int j = 0; j < 8; j++) {
            int n = bn + tx * 8 + j;
            biasv[j] = bi[n] + bh[n];
        }
#pragma unroll
        for (int i = 0; i < 8; i++) {
            size_t m = (size_t)(bm + ty * 8 + i);
            float r[8];
#pragma unroll
            for (int j = 0; j < 4; j++) {
                unsigned lo, hi;
                asm("mov.b64 {%0, %1}, %2;" : "=r"(lo), "=r"(hi) : "l"(acc2[i][j]));
                r[2 * j]     = __uint_as_float(lo) + biasv[2 * j];
                r[2 * j + 1] = __uint_as_float(hi) + biasv[2 * j + 1];
            }
            float4 v0 = make_float4(r[0], r[1], r[2], r[3]);
            float4 v1 = make_float4(r[4], r[5], r[6], r[7]);
            *(float4*)(g_hpre + m * HSZ + bn + tx * 8)     = v0;
            *(float4*)(g_hpre + m * HSZ + bn + tx * 8 + 4) = v1;
        }
    }
}

// ---------------------------------------------------------------------------
// Scan: cluster of 2 CTAs per FOUR batches. 576 threads/CTA:
//  wid 0-15 : hidden, warp w -> batch bl=w>>2, neuron quarter q=w&3
//  wid 16/17: output warps, each owns one of this CTA's two output batches.
// Warp-private spike lists, single mbarrier (count=34), no __syncthreads/step.
// ---------------------------------------------------------------------------
#define NTH 576
#define SCAN_SMEM_FLOATS 43586   // 174,344 bytes

__device__ __forceinline__ void st_peer_u32(uint32_t local_addr, uint32_t rank,
                                            uint32_t val) {
    asm volatile(
        "{.reg .b32 ra; mapa.shared::cluster.u32 ra, %0, %1;"
        " st.shared::cluster.b32 [ra], %2;}"
        :: "r"(local_addr), "r"(rank), "r"(val) : "memory");
}

__device__ __forceinline__ void mbar_arrive_local(uint32_t mbar) {
    asm volatile("mbarrier.arrive.release.cta.shared::cta.b64 _, [%0];"
                 :: "r"(mbar) : "memory");
}

__device__ __forceinline__ void mbar_arrive_peer(uint32_t mbar, uint32_t rank) {
    asm volatile(
        "{.reg .b32 ra; mapa.shared::cluster.u32 ra, %0, %1;"
        " mbarrier.arrive.release.cluster.shared::cluster.b64 _, [ra];}"
        :: "r"(mbar), "r"(rank) : "memory");
}

__device__ __forceinline__ void mbar_wait_parity(uint32_t mbar, uint32_t parity) {
    uint32_t done;
    asm volatile(
        "{\n\t.reg .pred p;\n\t"
        "mbarrier.try_wait.parity.acquire.cluster.shared::cta.b64 p, [%1], %2;\n\t"
        "selp.b32 %0, 1, 0, p;\n\t}"
        : "=r"(done) : "r"(mbar), "r"(parity) : "memory");
    if (!done) {
        asm volatile(
            "{\n\t.reg .pred P1;\n\t"
            "WL_%=:\n\t"
            "mbarrier.try_wait.parity.acquire.cluster.shared::cta.b64 P1, [%0], %1, 0x989680;\n\t"
            "@P1 bra.uni WD_%=;\n\t"
            "bra.uni WL_%=;\n\t"
            "WD_%=:\n\t}"
            :: "r"(mbar), "r"(parity) : "memory");
    }
}

__device__ __forceinline__ uint32_t smem_u32(const void* p) {
    uint32_t a;
    asm("{ .reg .u64 t; cvta.to.shared.u64 t, %1; cvt.u32.u64 %0, t; }"
        : "=r"(a) : "l"(p));
    return a;
}

#define TREE8(w0,w1,w2,w3,w4,w5,w6,w7) \
    (((w0 + w1) + (w2 + w3)) + ((w4 + w5) + (w6 + w7)))

// Warp-private scatter: ascending index list of set bits in w[0..7].
__device__ __forceinline__ int warp_scatter(const unsigned w[8], int lane,
                                            int* __restrict__ seg) {
    int cnt = 0;
#pragma unroll
    for (int k2 = 0; k2 < 8; k2++) cnt += __popc(w[k2]);

    const int wi = lane >> 2;
    const int bitbase = (lane & 3) * 8;
    int pos = 0;
#pragma unroll
    for (int k2 = 0; k2 < 8; k2++)
        if (k2 < wi) pos += __popc(w[k2]);
    unsigned myw = w[wi];
    pos += __popc(myw & ((1u << bitbase) - 1u));
    unsigned byte = (myw >> bitbase) & 0xffu;
    int base_n = lane * 8;
#pragma unroll
    for (int k2 = 0; k2 < 8; k2++) {
        if (byte & (1u << k2)) seg[pos++] = base_n + k2;
    }
    __syncwarp();
    return cnt;
}

// Gather: identical arithmetic order (8-wide trees, ascending), idx prefetch.
__device__ __forceinline__ float gather_list(const float* __restrict__ w,
                                             const int* __restrict__ lst,
                                             int cnt, int stride) {
    float racc = 0.f;
    int i = 0;
    if (cnt >= 8) {
        int4 ja = *(const int4*)(lst);
        int4 jb = *(const int4*)(lst + 4);
        float w0 = w[ja.x * stride], w1 = w[ja.y * stride];
        float w2 = w[ja.z * stride], w3 = w[ja.w * stride];
        float w4 = w[jb.x * stride], w5 = w[jb.y * stride];
        float w6 = w[jb.z * stride], w7 = w[jb.w * stride];
#pragma unroll 1
        for (i = 8; i + 8 <= cnt; i += 8) {
            int4 ja2 = *(const int4*)(lst + i);
            int4 jb2 = *(const int4*)(lst + i + 4);
            float v0 = w[ja2.x * stride], v1 = w[ja2.y * stride];
            float v2 = w[ja2.z * stride], v3 = w[ja2.w * stride];
            float v4 = w[jb2.x * stride], v5 = w[jb2.y * stride];
            float v6 = w[jb2.z * stride], v7 = w[jb2.w * stride];
            racc += TREE8(w0, w1, w2, w3, w4, w5, w6, w7);
            w0 = v0; w1 = v1; w2 = v2; w3 = v3;
            w4 = v4; w5 = v5; w6 = v6; w7 = v7;
        }
        racc += TREE8(w0, w1, w2, w3, w4, w5, w6, w7);
    }
#pragma unroll 1
    for (; i < cnt; ++i)
        racc += w[lst[i] * stride];
    return racc;
}

__global__ void __launch_bounds__(NTH, 1) __cluster_dims__(2, 1, 1)
scan_kernel(const float* __restrict__ Wo,
            const float* __restrict__ bo_bias,
            const float* __restrict__ tau_adp_o,
            const float* __restrict__ tau_m_h,
            const float* __restrict__ tau_m_o,
            const float* __restrict__ h0,
            const float* __restrict__ o0,
            float* __restrict__ out)
{
    extern __shared__ float smf[];
    float*    s_wt   = smf;                        // [256][128]  128 KB
    float*    s_woT  = smf + 32768;                // [256][20]
    float*    s_spk0 = smf + 37888;                // [4][256]
    int*      s_idx  = (int*)(smf + 38912);        // [18 warps][256]
    unsigned* s_bal  = (unsigned*)(smf + 43520);   // [2 par][4 batch][8]
    unsigned long long* s_mbar = (unsigned long long*)(smf + 43584);

    const int tid  = threadIdx.x;
    const int lane = tid & 31;
    const int wid  = tid >> 5;
    const int r    = blockIdx.x & 1;
    const int b0   = (blockIdx.x >> 1) * 4;        // first of 4 batches
    const bool hidden = (wid < 16);

    for (int i = tid; i < 8192; i += NTH) {
        int j = i >> 5, c = i & 31;
        ((float4*)s_wt)[i] =
            *(const float4*)(g_wth + (size_t)j * HSZ + r * 128 + c * 4);
    }
    for (int i = tid; i < OSZ * HSZ; i += NTH) {
        int o = i >> 8, j = i & 255;
        s_woT[j * OSZ + o] = Wo[i];
    }
    for (int i = tid; i < 4 * HSZ; i += NTH) {
        int bl2 = i >> 8, j = i & 255;
        s_spk0[i] = h0[(size_t)(b0 + bl2) * HSZ + j];
    }
    if (tid == 0) {
        asm volatile("mbarrier.init.shared.b64 [%0], %1;"
                     :: "r"(smem_u32(s_mbar)), "r"(34u) : "memory");
    }

    const int bl = (tid >> 7) & 3;                 // hidden batch-local (0..3)
    const int il = tid & 127;
    const int q  = (wid & 3);
    const int col = r * 128 + il;
    const int gw  = r * 4 + q;
    int* myseg = s_idx + wid * 256;

    float a_h = 0.f, one_m_ah = 0.f, h_mem = 0.f, spf = 0.f;
    if (hidden) {
        a_h = expf(-1.f / tau_m_h[col]);
        one_m_ah = 1.f - a_h;
        h_mem = h0[(size_t)(b0 + bl) * HSZ + col];
        spf = h_mem;
    }

    // output warps: wid16/17 own cluster batch blx = r*2 + (wid-16)
    const int blx = r * 2 + (wid - 16);
    const int ob  = b0 + blx;
    float o_mem = 0.f, o_spk = 0.f, bo = 0.f;
    float alpha_o = 0.f, ro_o = 0.f, one_m_ao = 0.f, one_m_ro = 0.f, bias_o = 0.f;
    if (!hidden && lane < OSZ) {
        o_mem    = o0[(size_t)ob * OSZ + lane];
        o_spk    = o_mem;
        bo       = BJ0;
        alpha_o  = expf(-1.f / tau_m_o[lane]);
        ro_o     = expf(-1.f / tau_adp_o[lane]);
        one_m_ao = 1.f - alpha_o;
        one_m_ro = 1.f - ro_o;
        bias_o   = bo_bias[lane];
    }
    __syncthreads();
    asm volatile("barrier.cluster.arrive.aligned;" ::: "memory");
    asm volatile("barrier.cluster.wait.aligned;" ::: "memory");

    const uint32_t bal_base = smem_u32(s_bal);
    const uint32_t mbar_u32 = smem_u32(s_mbar);

    if (hidden) {
        // =================== HIDDEN WARPS ===================
        const float* hp = g_hpre + ((size_t)(b0 + bl) * TLEN) * HSZ + col;
        const float* wcol = s_wt + il;
        float pre = __ldcs(hp);

#pragma unroll 1
        for (int t = 0; t < TLEN; ++t) {
            int cnt = 0;
            if (t >= 1) {
                mbar_wait_parity(mbar_u32, (t - 1) & 1);
                const unsigned* wp = s_bal + ((t - 1) & 1) * 32 + bl * 8;
                unsigned w[8];
#pragma unroll
                for (int k2 = 0; k2 < 8; k2++) w[k2] = wp[k2];
                cnt = warp_scatter(w, lane, myseg);
            }

            float acc = pre;
            if (t + 1 < TLEN) pre = __ldcs(hp + (size_t)(t + 1) * HSZ);

            float racc = 0.f;
            if (t == 0) {
                const float* sp0 = s_spk0 + bl * HSZ;
#pragma unroll 8
                for (int j = 0; j < HSZ; ++j)
                    racc += wcol[j * 128] * sp0[j];
            } else {
                racc = gather_list(wcol, myseg, cnt, 128);
            }
            acc += racc;

            h_mem = h_mem * a_h + one_m_ah * acc - BJ0 * spf;
            int sp = (h_mem - BJ0) > 0.f;
            spf = sp ? 1.f : 0.f;
            unsigned bal = __ballot_sync(0xffffffffu, sp);
            if (lane == 0) {
                int off = (t & 1) * 32 + bl * 8 + gw;
                s_bal[off] = bal;
                st_peer_u32(bal_base + off * 4, (unsigned)(r ^ 1), bal);
                mbar_arrive_local(mbar_u32);
                mbar_arrive_peer(mbar_u32, (unsigned)(r ^ 1));
            }
        }
    } else {
        // =================== OUTPUT WARPS (lag one step) ===================
        if (lane == 0) mbar_arrive_local(mbar_u32);   // prime phase 0

#pragma unroll 1
        for (int t = 1; t <= TLEN; ++t) {
            mbar_wait_parity(mbar_u32, (t - 1) & 1);
            const unsigned* wp = s_bal + ((t - 1) & 1) * 32 + blx * 8;
            unsigned w[8];
#pragma unroll
            for (int k2 = 0; k2 < 8; k2++) w[k2] = wp[k2];
            if (lane == 0 && t < TLEN) mbar_arrive_local(mbar_u32);

            int cnt = warp_scatter(w, lane, myseg);

            const int to = t - 1;
            float om;
            if (lane < OSZ) {
                float oin = bias_o + gather_list(s_woT + lane, myseg, cnt, OSZ);
                bo = ro_o * bo + one_m_ro * o_spk;
                float Bo = BJ0 + 1.8f * bo;
                o_mem = o_mem * alpha_o + one_m_ao * oin - Bo * o_spk;
                o_spk = ((o_mem - Bo) > 0.f) ? 1.f : 0.f;
                om = o_mem;
            } else {
                om = -CUDART_INF_F;
            }
            float mx = om;
#pragma unroll
            for (int off = 16; off; off >>= 1)
                mx = fmaxf(mx, __shfl_xor_sync(0xffffffffu, mx, off));
            float e = (lane < OSZ) ? __expf(om - mx) : 0.f;
            float s = e;
#pragma unroll
            for (int off = 16; off; off >>= 1)
                s += __shfl_xor_sync(0xffffffffu, s, off);
            if (lane < OSZ)
                out[((size_t)ob * OSZ + lane) * TLEN + to] = om - mx - __logf(s);
        }
    }

    asm volatile("barrier.cluster.arrive.aligned;" ::: "memory");
    asm volatile("barrier.cluster.wait.aligned;" ::: "memory");
}

// ---------------------------------------------------------------------------
extern "C" void kernel_launch(void* const* d_in, const int* in_sizes, int n_in,
                              void* d_out, int out_size) {
    const float* x         = (const float*)d_in[0];
    const float* W_i2h     = (const float*)d_in[1];
    const float* b_i2h     = (const float*)d_in[2];
    const float* W_h2h     = (const float*)d_in[3];
    const float* b_h2h     = (const float*)d_in[4];
    const float* W_h2o     = (const float*)d_in[5];
    const float* b_h2o     = (const float*)d_in[6];
    const float* tau_adp_o = (const float*)d_in[8];
    const float* tau_m_h   = (const float*)d_in[9];
    const float* tau_m_o   = (const float*)d_in[10];
    const float* h0        = (const float*)d_in[11];
    const float* o0        = (const float*)d_in[12];
    float* out = (float*)d_out;

    static int inited = 0;
    if (!inited) {
        cudaFuncSetAttribute(scan_kernel,
                             cudaFuncAttributeMaxDynamicSharedMemorySize,
                             SCAN_SMEM_FLOATS * 4);
        inited = 1;
    }

    prep_kernel<<<(ISZ * HSZ + 255) / 256, 256>>>(W_i2h, W_h2h);

    gemm_kernel<<<GEMM_GRID, 256>>>(x, b_i2h, b_h2h);

    scan_kernel<<<BSZ / 2, NTH, SCAN_SMEM_FLOATS * 4>>>(
        W_h2o, b_h2o, tau_adp_o, tau_m_h, tau_m_o, h0, o0, out);
}

// round 10
// speedup vs baseline: 1.1382x; 1.1382x over previous
#include <cuda_runtime.h>
#include <math.h>
#include <math_constants.h>
#include <stdint.h>

#define BSZ  128
#define TLEN 500
#define ISZ  700
#define HSZ  256
#define OSZ  20
#define BJ0  0.01f

// Scratch. g_hpre layout: [b][t][n]
__device__ float g_hpre[(size_t)BSZ * TLEN * HSZ];
__device__ float g_wit[ISZ * HSZ];                  // W_i2h^T [700][256]
__device__ float g_wth[HSZ * HSZ];                  // W_h2h^T [j][i]

// ---------------------------------------------------------------------------
__global__ void prep_kernel(const float* __restrict__ Wi,
                            const float* __restrict__ Wh) {
    int idx = blockIdx.x * blockDim.x + threadIdx.x;
    if (idx < ISZ * HSZ) {
        int k = idx / HSZ, n = idx % HSZ;
        g_wit[idx] = Wi[n * ISZ + k];
    }
    if (idx < HSZ * HSZ) {
        int j = idx / HSZ, i = idx % HSZ;
        g_wth[idx] = Wh[i * HSZ + j];
    }
}

// ---------------------------------------------------------------------------
// Persistent GEMM (R4 exact; bitwise-identical hpre)
// ---------------------------------------------------------------------------
#define FMA2(acc, a, b) \
    asm("fma.rn.f32x2 %0, %1, %2, %0;" : "+l"(acc) : "l"(a), "l"(b))

#define GEMM_TILES 1000
#define GEMM_GRID  296

__global__ void __launch_bounds__(256, 2) gemm_kernel(
    const float* __restrict__ A,
    const float* __restrict__ bi,
    const float* __restrict__ bh) {
    const int N = HSZ, K = ISZ;
    __shared__ __align__(16) float As[2][8][128];
    __shared__ __align__(16) float Bs[2][8][128];

    int tid = threadIdx.x;
    int tx = tid & 15, ty = tid >> 4;
    int arow  = tid >> 1,  acol4 = (tid & 1) * 4;
    int brow  = tid >> 5,  bcol4 = (tid & 31) * 4;

    for (int tile = blockIdx.x; tile < GEMM_TILES; tile += GEMM_GRID) {
        int bm = (tile >> 1) * 128;
        int bn = (tile & 1) * 128;
        const float* Aptr = A + (size_t)(bm + arow) * K;

        unsigned long long acc2[8][4];
#pragma unroll
        for (int i = 0; i < 8; i++)
#pragma unroll
            for (int j = 0; j < 4; j++) acc2[i][j] = 0ull;

        {
            float4 av = make_float4(0.f, 0.f, 0.f, 0.f);
            float4 bv = make_float4(0.f, 0.f, 0.f, 0.f);
            if (acol4 < K) av = *(const float4*)(Aptr + acol4);
            if (brow  < K) bv = *(const float4*)(g_wit + (size_t)brow * N + bn + bcol4);
            As[0][acol4 + 0][arow] = av.x;
            As[0][acol4 + 1][arow] = av.y;
            As[0][acol4 + 2][arow] = av.z;
            As[0][acol4 + 3][arow] = av.w;
            *(float4*)&Bs[0][brow][bcol4] = bv;
        }
        __syncthreads();

        int p = 0;
        for (int k0 = 0; k0 < K; k0 += 8) {
            bool more = (k0 + 8) < K;
            float4 av2 = make_float4(0.f, 0.f, 0.f, 0.f);
            float4 bv2 = make_float4(0.f, 0.f, 0.f, 0.f);
            if (more) {
                int ac = k0 + 8 + acol4;
                int bk = k0 + 8 + brow;
                if (ac < K) av2 = *(const float4*)(Aptr + ac);
                if (bk < K) bv2 = *(const float4*)(g_wit + (size_t)bk * N + bn + bcol4);
            }
#pragma unroll
            for (int kk = 0; kk < 8; kk++) {
                float4 a0 = *(const float4*)&As[p][kk][ty * 8];
                float4 a1 = *(const float4*)&As[p][kk][ty * 8 + 4];
                const unsigned long long* bp =
                    (const unsigned long long*)&Bs[p][kk][tx * 8];
                unsigned long long bb0 = bp[0], bb1 = bp[1], bb2 = bp[2], bb3 = bp[3];
                float af[8] = {a0.x, a0.y, a0.z, a0.w, a1.x, a1.y, a1.z, a1.w};
#pragma unroll
                for (int i = 0; i < 8; i++) {
                    unsigned long long aa;
                    unsigned ai = __float_as_uint(af[i]);
                    asm("mov.b64 %0, {%1, %1};" : "=l"(aa) : "r"(ai));
                    FMA2(acc2[i][0], aa, bb0);
                    FMA2(acc2[i][1], aa, bb1);
                    FMA2(acc2[i][2], aa, bb2);
                    FMA2(acc2[i][3], aa, bb3);
                }
            }
            if (more) {
                As[p ^ 1][acol4 + 0][arow] = av2.x;
                As[p ^ 1][acol4 + 1][arow] = av2.y;
                As[p ^ 1][acol4 + 2][arow] = av2.z;
                As[p ^ 1][acol4 + 3][arow] = av2.w;
                *(float4*)&Bs[p ^ 1][brow][bcol4] = bv2;
            }
            __syncthreads();
            p ^= 1;
        }

        float biasv[8];
#pragma unroll
        for (int j = 0; j < 8; j++) {
            int n = bn + tx * 8 + j;
            biasv[j] = bi[n] + bh[n];
        }
#pragma unroll
        for (int i = 0; i < 8; i++) {
            size_t m = (size_t)(bm + ty * 8 + i);
            float r[8];
#pragma unroll
            for (int j = 0; j < 4; j++) {
                unsigned lo, hi;
                asm("mov.b64 {%0, %1}, %2;" : "=r"(lo), "=r"(hi) : "l"(acc2[i][j]));
                r[2 * j]     = __uint_as_float(lo) + biasv[2 * j];
                r[2 * j + 1] = __uint_as_float(hi) + biasv[2 * j + 1];
            }
            float4 v0 = make_float4(r[0], r[1], r[2], r[3]);
            float4 v1 = make_float4(r[4], r[5], r[6], r[7]);
            *(float4*)(g_hpre + m * HSZ + bn + tx * 8)     = v0;
            *(float4*)(g_hpre + m * HSZ + bn + tx * 8 + 4) = v1;
        }
    }
}

// ---------------------------------------------------------------------------
// Scan: cluster of 2 CTAs per batch pair, 320 threads:
//   warps 0-7 : hidden (2 batches x 128 local neurons)
//   warp  8   : publisher (sends local ballot words to peer, arrives mbar)
//   warp  9   : output (lags one step; in mbar to gate ring reuse)
// Per step: local-half gather FIRST (needs only local named bar), cluster
// exchange hidden underneath, then peer-half gather after the mbar wait.
// Ballot ring 4-deep; mbar count=3 (local pub + peer pub + local output).
// ---------------------------------------------------------------------------
#define NTH 320
#define SCAN_SMEM_FLOATS 41026   // 164,104 bytes

__device__ __forceinline__ void st_peer_u32(uint32_t local_addr, uint32_t rank,
                                            uint32_t val) {
    asm volatile(
        "{.reg .b32 ra; mapa.shared::cluster.u32 ra, %0, %1;"
        " st.shared::cluster.b32 [ra], %2;}"
        :: "r"(local_addr), "r"(rank), "r"(val) : "memory");
}

__device__ __forceinline__ void mbar_arrive_local(uint32_t mbar) {
    asm volatile("mbarrier.arrive.release.cta.shared::cta.b64 _, [%0];"
                 :: "r"(mbar) : "memory");
}

__device__ __forceinline__ void mbar_arrive_peer(uint32_t mbar, uint32_t rank) {
    asm volatile(
        "{.reg .b32 ra; mapa.shared::cluster.u32 ra, %0, %1;"
        " mbarrier.arrive.release.cluster.shared::cluster.b64 _, [ra];}"
        :: "r"(mbar), "r"(rank) : "memory");
}

__device__ __forceinline__ void mbar_wait_parity(uint32_t mbar, uint32_t parity) {
    uint32_t done;
    asm volatile(
        "{\n\t.reg .pred p;\n\t"
        "mbarrier.try_wait.parity.acquire.cluster.shared::cta.b64 p, [%1], %2;\n\t"
        "selp.b32 %0, 1, 0, p;\n\t}"
        : "=r"(done) : "r"(mbar), "r"(parity) : "memory");
    if (!done) {
        asm volatile(
            "{\n\t.reg .pred P1;\n\t"
            "WL_%=:\n\t"
            "mbarrier.try_wait.parity.acquire.cluster.shared::cta.b64 P1, [%0], %1, 0x989680;\n\t"
            "@P1 bra.uni WD_%=;\n\t"
            "bra.uni WL_%=;\n\t"
            "WD_%=:\n\t}"
            :: "r"(mbar), "r"(parity) : "memory");
    }
}

__device__ __forceinline__ uint32_t smem_u32(const void* p) {
    uint32_t a;
    asm("{ .reg .u64 t; cvta.to.shared.u64 t, %1; cvt.u32.u64 %0, t; }"
        : "=r"(a) : "l"(p));
    return a;
}

#define BAR_HP_SYNC() \
    asm volatile("bar.sync 1, 288;" ::: "memory")   // hidden warps + publisher

#define TREE8(w0,w1,w2,w3,w4,w5,w6,w7) \
    (((w0 + w1) + (w2 + w3)) + ((w4 + w5) + (w6 + w7)))

// Scatter 4 ballot words (one 128-neuron half) -> ascending index list.
__device__ __forceinline__ int scatter4s(const unsigned* __restrict__ wp,
                                         int lane, int base,
                                         int* __restrict__ seg) {
    unsigned w0 = wp[0], w1 = wp[1], w2 = wp[2], w3 = wp[3];
    int cnt = __popc(w0) + __popc(w1) + __popc(w2) + __popc(w3);
    if (lane < 16) {
        const int wi = lane >> 2;
        const int bitbase = (lane & 3) * 8;
        int pos = 0;
        if (wi > 0) pos += __popc(w0);
        if (wi > 1) pos += __popc(w1);
        if (wi > 2) pos += __popc(w2);
        unsigned myw = (wi == 0) ? w0 : (wi == 1) ? w1 : (wi == 2) ? w2 : w3;
        pos += __popc(myw & ((1u << bitbase) - 1u));
        unsigned byte = (myw >> bitbase) & 0xffu;
        int bn = base + wi * 32 + bitbase;
#pragma unroll
        for (int k = 0; k < 8; k++)
            if (byte & (1u << k)) seg[pos++] = bn + k;
    }
    __syncwarp();
    return cnt;
}

// Full 8-word scatter (output warp, ascending over all 256).
__device__ __forceinline__ int warp_scatter8(const unsigned w[8], int lane,
                                             int* __restrict__ seg) {
    int cnt = 0;
#pragma unroll
    for (int k2 = 0; k2 < 8; k2++) cnt += __popc(w[k2]);
    const int wi = lane >> 2;
    const int bitbase = (lane & 3) * 8;
    int pos = 0;
#pragma unroll
    for (int k2 = 0; k2 < 8; k2++)
        if (k2 < wi) pos += __popc(w[k2]);
    unsigned myw = w[wi];
    pos += __popc(myw & ((1u << bitbase) - 1u));
    unsigned byte = (myw >> bitbase) & 0xffu;
    int base_n = lane * 8;
#pragma unroll
    for (int k2 = 0; k2 < 8; k2++)
        if (byte & (1u << k2)) seg[pos++] = base_n + k2;
    __syncwarp();
    return cnt;
}

// Gather: 8-wide trees, ascending, idx-prefetched (order as R7).
__device__ __forceinline__ float gather_list(const float* __restrict__ w,
                                             const int* __restrict__ lst,
                                             int cnt, int stride) {
    float racc = 0.f;
    int i = 0;
    if (cnt >= 8) {
        int4 ja = *(const int4*)(lst);
        int4 jb = *(const int4*)(lst + 4);
        float w0 = w[ja.x * stride], w1 = w[ja.y * stride];
        float w2 = w[ja.z * stride], w3 = w[ja.w * stride];
        float w4 = w[jb.x * stride], w5 = w[jb.y * stride];
        float w6 = w[jb.z * stride], w7 = w[jb.w * stride];
#pragma unroll 1
        for (i = 8; i + 8 <= cnt; i += 8) {
            int4 ja2 = *(const int4*)(lst + i);
            int4 jb2 = *(const int4*)(lst + i + 4);
            float v0 = w[ja2.x * stride], v1 = w[ja2.y * stride];
            float v2 = w[ja2.z * stride], v3 = w[ja2.w * stride];
            float v4 = w[jb2.x * stride], v5 = w[jb2.y * stride];
            float v6 = w[jb2.z * stride], v7 = w[jb2.w * stride];
            racc += TREE8(w0, w1, w2, w3, w4, w5, w6, w7);
            w0 = v0; w1 = v1; w2 = v2; w3 = v3;
            w4 = v4; w5 = v5; w6 = v6; w7 = v7;
        }
        racc += TREE8(w0, w1, w2, w3, w4, w5, w6, w7);
    }
#pragma unroll 1
    for (; i < cnt; ++i)
        racc += w[lst[i] * stride];
    return racc;
}

__global__ void __launch_bounds__(NTH, 1) __cluster_dims__(2, 1, 1)
scan_kernel(const float* __restrict__ Wo,
            const float* __restrict__ bo_bias,
            const float* __restrict__ tau_adp_o,
            const float* __restrict__ tau_m_h,
            const float* __restrict__ tau_m_o,
            const float* __restrict__ h0,
            const float* __restrict__ o0,
            float* __restrict__ out)
{
    extern __shared__ float smf[];
    float*    s_wt   = smf;                        // [256][128]
    float*    s_woT  = smf + 32768;                // [256][20]
    float*    s_spk0 = smf + 37888;                // [2][256]
    int*      s_idx  = (int*)(smf + 38400);        // [10 warps][256]
    unsigned* s_bal  = (unsigned*)(smf + 40960);   // [4 slot][2 batch][8]
    unsigned long long* s_mbar = (unsigned long long*)(smf + 41024);

    const int tid  = threadIdx.x;
    const int lane = tid & 31;
    const int wid  = tid >> 5;
    const int r    = blockIdx.x & 1;
    const int b0   = blockIdx.x & ~1;
    const bool hidden = (wid < 8);

    for (int i = tid; i < 8192; i += NTH) {
        int j = i >> 5, c = i & 31;
        ((float4*)s_wt)[i] =
            *(const float4*)(g_wth + (size_t)j * HSZ + r * 128 + c * 4);
    }
    for (int i = tid; i < OSZ * HSZ; i += NTH) {
        int o = i >> 8, j = i & 255;
        s_woT[j * OSZ + o] = Wo[i];
    }
    for (int i = tid; i < 2 * HSZ; i += NTH) {
        int bl2 = i >> 8, j = i & 255;
        s_spk0[i] = h0[(size_t)(b0 + bl2) * HSZ + j];
    }
    if (tid == 0) {
        asm volatile("mbarrier.init.shared.b64 [%0], %1;"
                     :: "r"(smem_u32(s_mbar)), "r"(3u) : "memory");
    }

    const int bl = (tid >> 7) & 1;                 // hidden batch-local
    const int il = tid & 127;
    const int q  = (wid & 3);
    const int col = r * 128 + il;
    const int gw  = r * 4 + q;                     // my global ballot word
    int* myseg = s_idx + wid * 256;

    float a_h = 0.f, one_m_ah = 0.f, h_mem = 0.f, spf = 0.f;
    if (hidden) {
        a_h = expf(-1.f / tau_m_h[col]);
        one_m_ah = 1.f - a_h;
        h_mem = h0[(size_t)(b0 + bl) * HSZ + col];
        spf = h_mem;
    }

    float o_mem = 0.f, o_spk = 0.f, bo = 0.f;
    float alpha_o = 0.f, ro_o = 0.f, one_m_ao = 0.f, one_m_ro = 0.f, bias_o = 0.f;
    if (wid == 9 && lane < OSZ) {
        o_mem    = o0[(size_t)blockIdx.x * OSZ + lane];
        o_spk    = o_mem;
        bo       = BJ0;
        alpha_o  = expf(-1.f / tau_m_o[lane]);
        ro_o     = expf(-1.f / tau_adp_o[lane]);
        one_m_ao = 1.f - alpha_o;
        one_m_ro = 1.f - ro_o;
        bias_o   = bo_bias[lane];
    }
    __syncthreads();
    asm volatile("barrier.cluster.arrive.aligned;" ::: "memory");
    asm volatile("barrier.cluster.wait.aligned;" ::: "memory");

    const uint32_t bal_base = smem_u32(s_bal);
    const uint32_t mbar_u32 = smem_u32(s_mbar);

    if (hidden) {
        // =================== HIDDEN WARPS ===================
        const float* hp = g_hpre + ((size_t)(b0 + bl) * TLEN) * HSZ + col;
        const float* wcol = s_wt + il;
        float pre = __ldcs(hp);

#pragma unroll 1
        for (int t = 0; t < TLEN; ++t) {
            float racc;
            if (t == 0) {
                const float* sp0 = s_spk0 + bl * HSZ;
                racc = 0.f;
#pragma unroll 8
                for (int j = 0; j < HSZ; ++j)
                    racc += wcol[j * 128] * sp0[j];
            } else {
                const unsigned* wp =
                    s_bal + ((t - 1) & 3) * 16 + bl * 8;
                // local half first (visible since end-of-iter bar of t-1)
                int cl = scatter4s(wp + r * 4, lane, r * 128, myseg);
                float rl = gather_list(wcol, myseg, cl, 128);
                // peer half after mbar (exchange overlapped with local gather)
                mbar_wait_parity(mbar_u32, (t - 1) & 1);
                int cp = scatter4s(wp + (r ^ 1) * 4, lane, (r ^ 1) * 128, myseg);
                float rp = gather_list(wcol, myseg, cp, 128);
                racc = rl + rp;
            }

            float acc = pre + racc;
            if (t + 1 < TLEN) pre = __ldcs(hp + (size_t)(t + 1) * HSZ);

            h_mem = h_mem * a_h + one_m_ah * acc - BJ0 * spf;
            int sp = (h_mem - BJ0) > 0.f;
            spf = sp ? 1.f : 0.f;
            unsigned bal = __ballot_sync(0xffffffffu, sp);
            if (lane == 0)
                s_bal[(t & 3) * 16 + bl * 8 + gw] = bal;
            BAR_HP_SYNC();
        }
    } else if (wid == 8) {
        // =================== PUBLISHER WARP ===================
#pragma unroll 1
        for (int t = 0; t < TLEN; ++t) {
            BAR_HP_SYNC();                    // local ballots of step t ready
            if (lane == 0) {
                int base = (t & 3) * 16;
#pragma unroll
                for (int b2 = 0; b2 < 2; b2++) {
#pragma unroll
                    for (int k2 = 0; k2 < 4; k2++) {
                        int off = base + b2 * 8 + r * 4 + k2;
                        st_peer_u32(bal_base + off * 4, (unsigned)(r ^ 1),
                                    s_bal[off]);
                    }
                }
                mbar_arrive_peer(mbar_u32, (unsigned)(r ^ 1));
                mbar_arrive_local(mbar_u32);
            }
        }
    } else {
        // =================== OUTPUT WARP (lags; gates ring reuse) =========
        if (lane == 0) mbar_arrive_local(mbar_u32);   // prime phase 0

#pragma unroll 1
        for (int to = 0; to < TLEN; ++to) {
            mbar_wait_parity(mbar_u32, to & 1);
            const unsigned* wp = s_bal + (to & 3) * 16 + r * 8;
            unsigned w[8];
#pragma unroll
            for (int k2 = 0; k2 < 8; k2++) w[k2] = wp[k2];
            if (lane == 0 && to < TLEN - 1) mbar_arrive_local(mbar_u32);

            int cnt = warp_scatter8(w, lane, myseg);

            float om;
            if (lane < OSZ) {
                float oin = bias_o + gather_list(s_woT + lane, myseg, cnt, OSZ);
                bo = ro_o * bo + one_m_ro * o_spk;
                float Bo = BJ0 + 1.8f * bo;
                o_mem = o_mem * alpha_o + one_m_ao * oin - Bo * o_spk;
                o_spk = ((o_mem - Bo) > 0.f) ? 1.f : 0.f;
                om = o_mem;
            } else {
                om = -CUDART_INF_F;
            }
            float mx = om;
#pragma unroll
            for (int off = 16; off; off >>= 1)
                mx = fmaxf(mx, __shfl_xor_sync(0xffffffffu, mx, off));
            float e = (lane < OSZ) ? __expf(om - mx) : 0.f;
            float s = e;
#pragma unroll
            for (int off = 16; off; off >>= 1)
                s += __shfl_xor_sync(0xffffffffu, s, off);
            if (lane < OSZ)
                out[((size_t)blockIdx.x * OSZ + lane) * TLEN + to] =
                    om - mx - __logf(s);
        }
    }

    asm volatile("barrier.cluster.arrive.aligned;" ::: "memory");
    asm volatile("barrier.cluster.wait.aligned;" ::: "memory");
}

// ---------------------------------------------------------------------------
extern "C" void kernel_launch(void* const* d_in, const int* in_sizes, int n_in,
                              void* d_out, int out_size) {
    const float* x         = (const float*)d_in[0];
    const float* W_i2h     = (const float*)d_in[1];
    const float* b_i2h     = (const float*)d_in[2];
    const float* W_h2h     = (const float*)d_in[3];
    const float* b_h2h     = (const float*)d_in[4];
    const float* W_h2o     = (const float*)d_in[5];
    const float* b_h2o     = (const float*)d_in[6];
    const float* tau_adp_o = (const float*)d_in[8];
    const float* tau_m_h   = (const float*)d_in[9];
    const float* tau_m_o   = (const float*)d_in[10];
    const float* h0        = (const float*)d_in[11];
    const float* o0        = (const float*)d_in[12];
    float* out = (float*)d_out;

    static int inited = 0;
    if (!inited) {
        cudaFuncSetAttribute(scan_kernel,
                             cudaFuncAttributeMaxDynamicSharedMemorySize,
                             SCAN_SMEM_FLOATS * 4);
        inited = 1;
    }

    prep_kernel<<<(ISZ * HSZ + 255) / 256, 256>>>(W_i2h, W_h2h);

    gemm_kernel<<<GEMM_GRID, 256>>>(x, b_i2h, b_h2h);

    scan_kernel<<<BSZ, NTH, SCAN_SMEM_FLOATS * 4>>>(
        W_h2o, b_h2o, tau_adp_o, tau_m_h, tau_m_o, h0, o0, out);
}

// round 11
// speedup vs baseline: 1.2434x; 1.0925x over previous
#include <cuda_runtime.h>
#include <math.h>
#include <math_constants.h>
#include <stdint.h>

#define BSZ  128
#define TLEN 500
#define ISZ  700
#define HSZ  256
#define OSZ  20
#define BJ0  0.01f

// Scratch. g_hpre layout: [b][t][n]
__device__ float    g_hpre[(size_t)BSZ * TLEN * HSZ];
__device__ float    g_wit[ISZ * HSZ];               // W_i2h^T [700][256]
__device__ float    g_wth[HSZ * HSZ];               // W_h2h^T [j][i]
__device__ unsigned g_ball[(size_t)BSZ * TLEN * 8]; // spike masks [b][t][8]
__device__ float    g_oin[(size_t)BSZ * TLEN * OSZ];
__device__ float    g_om [(size_t)BSZ * TLEN * OSZ];

// ---------------------------------------------------------------------------
__global__ void prep_kernel(const float* __restrict__ Wi,
                            const float* __restrict__ Wh) {
    int idx = blockIdx.x * blockDim.x + threadIdx.x;
    if (idx < ISZ * HSZ) {
        int k = idx / HSZ, n = idx % HSZ;
        g_wit[idx] = Wi[n * ISZ + k];
    }
    if (idx < HSZ * HSZ) {
        int j = idx / HSZ, i = idx % HSZ;
        g_wth[idx] = Wh[i * HSZ + j];
    }
}

// ---------------------------------------------------------------------------
// Persistent GEMM (R4 exact; bitwise-identical hpre)
// ---------------------------------------------------------------------------
#define FMA2(acc, a, b) \
    asm("fma.rn.f32x2 %0, %1, %2, %0;" : "+l"(acc) : "l"(a), "l"(b))

#define GEMM_TILES 1000
#define GEMM_GRID  296

__global__ void __launch_bounds__(256, 2) gemm_kernel(
    const float* __restrict__ A,
    const float* __restrict__ bi,
    const float* __restrict__ bh) {
    const int N = HSZ, K = ISZ;
    __shared__ __align__(16) float As[2][8][128];
    __shared__ __align__(16) float Bs[2][8][128];

    int tid = threadIdx.x;
    int tx = tid & 15, ty = tid >> 4;
    int arow  = tid >> 1,  acol4 = (tid & 1) * 4;
    int brow  = tid >> 5,  bcol4 = (tid & 31) * 4;

    for (int tile = blockIdx.x; tile < GEMM_TILES; tile += GEMM_GRID) {
        int bm = (tile >> 1) * 128;
        int bn = (tile & 1) * 128;
        const float* Aptr = A + (size_t)(bm + arow) * K;

        unsigned long long acc2[8][4];
#pragma unroll
        for (int i = 0; i < 8; i++)
#pragma unroll
            for (int j = 0; j < 4; j++) acc2[i][j] = 0ull;

        {
            float4 av = make_float4(0.f, 0.f, 0.f, 0.f);
            float4 bv = make_float4(0.f, 0.f, 0.f, 0.f);
            if (acol4 < K) av = *(const float4*)(Aptr + acol4);
            if (brow  < K) bv = *(const float4*)(g_wit + (size_t)brow * N + bn + bcol4);
            As[0][acol4 + 0][arow] = av.x;
            As[0][acol4 + 1][arow] = av.y;
            As[0][acol4 + 2][arow] = av.z;
            As[0][acol4 + 3][arow] = av.w;
            *(float4*)&Bs[0][brow][bcol4] = bv;
        }
        __syncthreads();

        int p = 0;
        for (int k0 = 0; k0 < K; k0 += 8) {
            bool more = (k0 + 8) < K;
            float4 av2 = make_float4(0.f, 0.f, 0.f, 0.f);
            float4 bv2 = make_float4(0.f, 0.f, 0.f, 0.f);
            if (more) {
                int ac = k0 + 8 + acol4;
                int bk = k0 + 8 + brow;
                if (ac < K) av2 = *(const float4*)(Aptr + ac);
                if (bk < K) bv2 = *(const float4*)(g_wit + (size_t)bk * N + bn + bcol4);
            }
#pragma unroll
            for (int kk = 0; kk < 8; kk++) {
                float4 a0 = *(const float4*)&As[p][kk][ty * 8];
                float4 a1 = *(const float4*)&As[p][kk][ty * 8 + 4];
                const unsigned long long* bp =
                    (const unsigned long long*)&Bs[p][kk][tx * 8];
                unsigned long long bb0 = bp[0], bb1 = bp[1], bb2 = bp[2], bb3 = bp[3];
                float af[8] = {a0.x, a0.y, a0.z, a0.w, a1.x, a1.y, a1.z, a1.w};
#pragma unroll
                for (int i = 0; i < 8; i++) {
                    unsigned long long aa;
                    unsigned ai = __float_as_uint(af[i]);
                    asm("mov.b64 %0, {%1, %1};" : "=l"(aa) : "r"(ai));
                    FMA2(acc2[i][0], aa, bb0);
                    FMA2(acc2[i][1], aa, bb1);
                    FMA2(acc2[i][2], aa, bb2);
                    FMA2(acc2[i][3], aa, bb3);
                }
            }
            if (more) {
                As[p ^ 1][acol4 + 0][arow] = av2.x;
                As[p ^ 1][acol4 + 1][arow] = av2.y;
                As[p ^ 1][acol4 + 2][arow] = av2.z;
                As[p ^ 1][acol4 + 3][arow] = av2.w;
                *(float4*)&Bs[p ^ 1][brow][bcol4] = bv2;
            }
            __syncthreads();
            p ^= 1;
        }

        float biasv[8];
#pragma unroll
        for (int j = 0; j < 8; j++) {
            int n = bn + tx * 8 + j;
            biasv[j] = bi[n] + bh[n];
        }
#pragma unroll
        for (int i = 0; i < 8; i++) {
            size_t m = (size_t)(bm + ty * 8 + i);
            float r[8];
#pragma unroll
            for (int j = 0; j < 4; j++) {
                unsigned lo, hi;
                asm("mov.b64 {%0, %1}, %2;" : "=r"(lo), "=r"(hi) : "l"(acc2[i][j]));
                r[2 * j]     = __uint_as_float(lo) + biasv[2 * j];
                r[2 * j + 1] = __uint_as_float(hi) + biasv[2 * j + 1];
            }
            float4 v0 = make_float4(r[0], r[1], r[2], r[3]);
            float4 v1 = make_float4(r[4], r[5], r[6], r[7]);
            *(float4*)(g_hpre + m * HSZ + bn + tx * 8)     = v0;
            *(float4*)(g_hpre + m * HSZ + bn + tx * 8 + 4) = v1;
        }
    }
}

// ---------------------------------------------------------------------------
// Shared helpers
// ---------------------------------------------------------------------------
__device__ __forceinline__ void st_peer_u32(uint32_t local_addr, uint32_t rank,
                                            uint32_t val) {
    asm volatile(
        "{.reg .b32 ra; mapa.shared::cluster.u32 ra, %0, %1;"
        " st.shared::cluster.b32 [ra], %2;}"
        :: "r"(local_addr), "r"(rank), "r"(val) : "memory");
}

__device__ __forceinline__ void mbar_arrive_local(uint32_t mbar) {
    asm volatile("mbarrier.arrive.release.cta.shared::cta.b64 _, [%0];"
                 :: "r"(mbar) : "memory");
}

__device__ __forceinline__ void mbar_arrive_peer(uint32_t mbar, uint32_t rank) {
    asm volatile(
        "{.reg .b32 ra; mapa.shared::cluster.u32 ra, %0, %1;"
        " mbarrier.arrive.release.cluster.shared::cluster.b64 _, [ra];}"
        :: "r"(mbar), "r"(rank) : "memory");
}

__device__ __forceinline__ void mbar_wait_parity(uint32_t mbar, uint32_t parity) {
    uint32_t done;
    asm volatile(
        "{\n\t.reg .pred p;\n\t"
        "mbarrier.try_wait.parity.acquire.cluster.shared::cta.b64 p, [%1], %2;\n\t"
        "selp.b32 %0, 1, 0, p;\n\t}"
        : "=r"(done) : "r"(mbar), "r"(parity) : "memory");
    if (!done) {
        asm volatile(
            "{\n\t.reg .pred P1;\n\t"
            "WL_%=:\n\t"
            "mbarrier.try_wait.parity.acquire.cluster.shared::cta.b64 P1, [%0], %1, 0x989680;\n\t"
            "@P1 bra.uni WD_%=;\n\t"
            "bra.uni WL_%=;\n\t"
            "WD_%=:\n\t}"
            :: "r"(mbar), "r"(parity) : "memory");
    }
}

__device__ __forceinline__ uint32_t smem_u32(const void* p) {
    uint32_t a;
    asm("{ .reg .u64 t; cvta.to.shared.u64 t, %1; cvt.u32.u64 %0, t; }"
        : "=r"(a) : "l"(p));
    return a;
}

#define TREE8(w0,w1,w2,w3,w4,w5,w6,w7) \
    (((w0 + w1) + (w2 + w3)) + ((w4 + w5) + (w6 + w7)))

// Warp-private scatter: ascending index list of set bits in w[0..7].
__device__ __forceinline__ int warp_scatter8(const unsigned w[8], int lane,
                                             int* __restrict__ seg) {
    int cnt = 0;
#pragma unroll
    for (int k2 = 0; k2 < 8; k2++) cnt += __popc(w[k2]);
    const int wi = lane >> 2;
    const int bitbase = (lane & 3) * 8;
    int pos = 0;
#pragma unroll
    for (int k2 = 0; k2 < 8; k2++)
        if (k2 < wi) pos += __popc(w[k2]);
    unsigned myw = w[wi];
    pos += __popc(myw & ((1u << bitbase) - 1u));
    unsigned byte = (myw >> bitbase) & 0xffu;
    int base_n = lane * 8;
#pragma unroll
    for (int k2 = 0; k2 < 8; k2++)
        if (byte & (1u << k2)) seg[pos++] = base_n + k2;
    __syncwarp();
    return cnt;
}

// 16-wide gather: same add ORDER as the 8-wide version (racc+=T1; racc+=T2),
// but 16 loads in flight per iteration.
__device__ __forceinline__ float gather_list16(const float* __restrict__ w,
                                               const int* __restrict__ lst,
                                               int cnt, int stride) {
    float racc = 0.f;
    int i = 0;
#pragma unroll 1
    for (; i + 16 <= cnt; i += 16) {
        int4 ja = *(const int4*)(lst + i);
        int4 jb = *(const int4*)(lst + i + 4);
        int4 jc = *(const int4*)(lst + i + 8);
        int4 jd = *(const int4*)(lst + i + 12);
        float w0 = w[ja.x * stride], w1 = w[ja.y * stride];
        float w2 = w[ja.z * stride], w3 = w[ja.w * stride];
        float w4 = w[jb.x * stride], w5 = w[jb.y * stride];
        float w6 = w[jb.z * stride], w7 = w[jb.w * stride];
        float x0 = w[jc.x * stride], x1 = w[jc.y * stride];
        float x2 = w[jc.z * stride], x3 = w[jc.w * stride];
        float x4 = w[jd.x * stride], x5 = w[jd.y * stride];
        float x6 = w[jd.z * stride], x7 = w[jd.w * stride];
        float t1 = TREE8(w0, w1, w2, w3, w4, w5, w6, w7);
        float t2 = TREE8(x0, x1, x2, x3, x4, x5, x6, x7);
        racc += t1;
        racc += t2;
    }
    if (i + 8 <= cnt) {
        int4 ja = *(const int4*)(lst + i);
        int4 jb = *(const int4*)(lst + i + 4);
        float w0 = w[ja.x * stride], w1 = w[ja.y * stride];
        float w2 = w[ja.z * stride], w3 = w[ja.w * stride];
        float w4 = w[jb.x * stride], w5 = w[jb.y * stride];
        float w6 = w[jb.z * stride], w7 = w[jb.w * stride];
        racc += TREE8(w0, w1, w2, w3, w4, w5, w6, w7);
        i += 8;
    }
#pragma unroll 1
    for (; i < cnt; ++i)
        racc += w[lst[i] * stride];
    return racc;
}

// ---------------------------------------------------------------------------
// Scan: cluster of 2 CTAs per batch pair, 256 threads = 8 hidden warps
// (perfectly balanced 2/SMSP). No output warp: spike masks stored to g_ball
// for a post-pass. mbarrier count = 16 (8 local + 8 peer lane0 arrives).
// ---------------------------------------------------------------------------
#define NTH 256
#define SCAN_SMEM_FLOATS 35368   // 141,472 bytes

__global__ void __launch_bounds__(NTH, 1) __cluster_dims__(2, 1, 1)
scan_kernel(const float* __restrict__ tau_m_h,
            const float* __restrict__ h0)
{
    extern __shared__ float smf[];
    float*    s_wt   = smf;                        // [256][128] 128 KB
    float*    s_spk0 = smf + 32768;                // [2][256]
    int*      s_idx  = (int*)(smf + 33280);        // [8 warps][256]
    unsigned* s_bal  = (unsigned*)(smf + 35328);   // [2 par][2 batch][8]
    unsigned long long* s_mbar = (unsigned long long*)(smf + 35360);

    const int tid  = threadIdx.x;
    const int lane = tid & 31;
    const int wid  = tid >> 5;
    const int r    = blockIdx.x & 1;
    const int b0   = blockIdx.x & ~1;

    for (int i = tid; i < 8192; i += NTH) {
        int j = i >> 5, c = i & 31;
        ((float4*)s_wt)[i] =
            *(const float4*)(g_wth + (size_t)j * HSZ + r * 128 + c * 4);
    }
    for (int i = tid; i < 2 * HSZ; i += NTH) {
        int bl2 = i >> 8, j = i & 255;
        s_spk0[i] = h0[(size_t)(b0 + bl2) * HSZ + j];
    }
    if (tid == 0) {
        asm volatile("mbarrier.init.shared.b64 [%0], %1;"
                     :: "r"(smem_u32(s_mbar)), "r"(16u) : "memory");
    }

    const int bl = (tid >> 7) & 1;
    const int il = tid & 127;
    const int q  = (wid & 3);
    const int col = r * 128 + il;
    const int gw  = r * 4 + q;
    int* myseg = s_idx + wid * 256;

    const float a_h      = expf(-1.f / tau_m_h[col]);
    const float one_m_ah = 1.f - a_h;
    float h_mem = h0[(size_t)(b0 + bl) * HSZ + col];
    float spf   = h_mem;

    __syncthreads();
    asm volatile("barrier.cluster.arrive.aligned;" ::: "memory");
    asm volatile("barrier.cluster.wait.aligned;" ::: "memory");

    const uint32_t bal_base = smem_u32(s_bal);
    const uint32_t mbar_u32 = smem_u32(s_mbar);

    const float* hp = g_hpre + ((size_t)(b0 + bl) * TLEN) * HSZ + col;
    const float* wcol = s_wt + il;
    float pre = __ldcs(hp);
    unsigned* gb = g_ball + ((size_t)(b0 + bl) * TLEN) * 8 + gw;

#pragma unroll 1
    for (int t = 0; t < TLEN; ++t) {
        int cnt = 0;
        if (t >= 1) {
            mbar_wait_parity(mbar_u32, (t - 1) & 1);
            const unsigned* wp = s_bal + ((t - 1) & 1) * 16 + bl * 8;
            unsigned w[8];
#pragma unroll
            for (int k2 = 0; k2 < 8; k2++) w[k2] = wp[k2];
            cnt = warp_scatter8(w, lane, myseg);
        }

        float acc = pre;
        if (t + 1 < TLEN) pre = __ldcs(hp + (size_t)(t + 1) * HSZ);

        float racc;
        if (t == 0) {
            const float* sp0 = s_spk0 + bl * HSZ;
            racc = 0.f;
#pragma unroll 8
            for (int j = 0; j < HSZ; ++j)
                racc += wcol[j * 128] * sp0[j];
        } else {
            racc = gather_list16(wcol, myseg, cnt, 128);
        }
        acc += racc;

        h_mem = h_mem * a_h + one_m_ah * acc - BJ0 * spf;
        int sp = (h_mem - BJ0) > 0.f;
        spf = sp ? 1.f : 0.f;
        unsigned bal = __ballot_sync(0xffffffffu, sp);
        if (lane == 0) {
            int off = (t & 1) * 16 + bl * 8 + gw;
            s_bal[off] = bal;
            st_peer_u32(bal_base + off * 4, (unsigned)(r ^ 1), bal);
            mbar_arrive_local(mbar_u32);
            mbar_arrive_peer(mbar_u32, (unsigned)(r ^ 1));
            __stcs(gb + (size_t)t * 8, bal);   // for the output post-pass
        }
    }

    asm volatile("barrier.cluster.arrive.aligned;" ::: "memory");
    asm volatile("barrier.cluster.wait.aligned;" ::: "memory");
}

// ---------------------------------------------------------------------------
// Post-pass A: oin[b][t][o] = sum over spiking j of Wo^T[j][o]
// (gather order identical to the scan-resident output warp -> bitwise same)
// ---------------------------------------------------------------------------
__global__ void __launch_bounds__(128) oin_kernel(const float* __restrict__ Wo) {
    __shared__ float s_woT[HSZ * OSZ];     // [j][o], 20 KB
    __shared__ int   s_list[4][256];

    int tid = threadIdx.x, lane = tid & 31, wid = tid >> 5;
    for (int i = tid; i < OSZ * HSZ; i += 128) {
        int o = i >> 8, j = i & 255;
        s_woT[j * OSZ + o] = Wo[i];
    }
    __syncthreads();

    int task = blockIdx.x * 4 + wid;       // = b*TLEN + t, < 64000
    const unsigned* gb = g_ball + (size_t)task * 8;
    unsigned w[8];
#pragma unroll
    for (int k = 0; k < 8; k++) w[k] = gb[k];
    int cnt = warp_scatter8(w, lane, s_list[wid]);
    if (lane < OSZ) {
        float v = gather_list16(s_woT + lane, s_list[wid], cnt, OSZ);
        g_oin[(size_t)task * OSZ + lane] = v;
    }
}

// ---------------------------------------------------------------------------
// Post-pass B: per-(b,o) ALIF recurrence over t (2560 threads)
// ---------------------------------------------------------------------------
__global__ void __launch_bounds__(256) orec_kernel(
    const float* __restrict__ bo_bias,
    const float* __restrict__ tau_adp_o,
    const float* __restrict__ tau_m_o,
    const float* __restrict__ o0) {
    int gt = blockIdx.x * blockDim.x + threadIdx.x;
    if (gt >= BSZ * OSZ) return;
    int b = gt / OSZ, o = gt % OSZ;

    const float alpha = expf(-1.f / tau_m_o[o]);
    const float ro    = expf(-1.f / tau_adp_o[o]);
    const float oma   = 1.f - alpha;
    const float omr   = 1.f - ro;
    const float bias  = bo_bias[o];

    float om  = o0[(size_t)b * OSZ + o];
    float osp = om;
    float bo  = BJ0;

    const float* oi = g_oin + (size_t)b * TLEN * OSZ + o;
    float*       od = g_om  + (size_t)b * TLEN * OSZ + o;
    float pre = oi[0];
#pragma unroll 1
    for (int t = 0; t < TLEN; ++t) {
        float oin = bias + pre;
        if (t + 1 < TLEN) pre = oi[(size_t)(t + 1) * OSZ];
        bo = ro * bo + omr * osp;
        float Bo = BJ0 + 1.8f * bo;
        om = om * alpha + oma * oin - Bo * osp;
        osp = ((om - Bo) > 0.f) ? 1.f : 0.f;
        od[(size_t)t * OSZ] = om;
    }
}

// ---------------------------------------------------------------------------
// Post-pass C: log-softmax per (b,t), one warp each (same shuffle order as R7)
// ---------------------------------------------------------------------------
__global__ void __launch_bounds__(256) softmax_kernel(float* __restrict__ out) {
    int lane = threadIdx.x & 31, wid = threadIdx.x >> 5;
    int task = blockIdx.x * 8 + wid;       // = b*TLEN + t
    int b = task / TLEN, t = task % TLEN;

    float om = (lane < OSZ) ? g_om[(size_t)task * OSZ + lane] : -CUDART_INF_F;
    float mx = om;
#pragma unroll
    for (int off = 16; off; off >>= 1)
        mx = fmaxf(mx, __shfl_xor_sync(0xffffffffu, mx, off));
    float e = (lane < OSZ) ? __expf(om - mx) : 0.f;
    float s = e;
#pragma unroll
    for (int off = 16; off; off >>= 1)
        s += __shfl_xor_sync(0xffffffffu, s, off);
    if (lane < OSZ)
        out[((size_t)b * OSZ + lane) * TLEN + t] = om - mx - __logf(s);
}

// ---------------------------------------------------------------------------
extern "C" void kernel_launch(void* const* d_in, const int* in_sizes, int n_in,
                              void* d_out, int out_size) {
    const float* x         = (const float*)d_in[0];
    const float* W_i2h     = (const float*)d_in[1];
    const float* b_i2h     = (const float*)d_in[2];
    const float* W_h2h     = (const float*)d_in[3];
    const float* b_h2h     = (const float*)d_in[4];
    const float* W_h2o     = (const float*)d_in[5];
    const float* b_h2o     = (const float*)d_in[6];
    const float* tau_adp_o = (const float*)d_in[8];
    const float* tau_m_h   = (const float*)d_in[9];
    const float* tau_m_o   = (const float*)d_in[10];
    const float* h0        = (const float*)d_in[11];
    const float* o0        = (const float*)d_in[12];
    float* out = (float*)d_out;

    static int inited = 0;
    if (!inited) {
        cudaFuncSetAttribute(scan_kernel,
                             cudaFuncAttributeMaxDynamicSharedMemorySize,
                             SCAN_SMEM_FLOATS * 4);
        inited = 1;
    }

    prep_kernel<<<(ISZ * HSZ + 255) / 256, 256>>>(W_i2h, W_h2h);

    gemm_kernel<<<GEMM_GRID, 256>>>(x, b_i2h, b_h2h);

    scan_kernel<<<BSZ, NTH, SCAN_SMEM_FLOATS * 4>>>(tau_m_h, h0);

    oin_kernel<<<BSZ * TLEN / 4, 128>>>(W_h2o);

    orec_kernel<<<(BSZ * OSZ + 255) / 256, 256>>>(b_h2o, tau_adp_o, tau_m_o, o0);

    softmax_kernel<<<BSZ * TLEN / 8, 256>>>(out);
}